// round 16
// baseline (speedup 1.0000x reference)
#include <cuda_runtime.h>

#define E_TOTAL   20000
#define FDIM      17
#define TILE_E    40
#define CO_TILE   8
#define W3S_ROWS  768          // CO_TILE*32*3
#define B_PITCH   36           // [dd][di] triples, 16B-aligned: dd*12+di*4+q
// smem: w3s (xor-swizzled, pitch 32) + h + B + R bounce buffer
#define SMEM_FLOATS (W3S_ROWS*32 + TILE_E*32 + TILE_E*B_PITCH + 256*4)
#define SMEM_BYTES  (SMEM_FLOATS * 4)

// scratch for h2 (radial MLP output), allocation-free per harness rules
__device__ float g_h[E_TOTAL * 32];

// ---------------------------------------------------------------------------
// Kernel 1: radial MLP  f[E,17] -> h2[E,32]. One warp per edge.
// ---------------------------------------------------------------------------
__global__ __launch_bounds__(256) void mlp_kernel(
    const float* __restrict__ f,
    const float* __restrict__ w1, const float* __restrict__ b1,
    const float* __restrict__ g1, const float* __restrict__ be1,
    const float* __restrict__ w2, const float* __restrict__ b2,
    const float* __restrict__ g2, const float* __restrict__ be2)
{
    __shared__ float w1s[32 * FDIM];
    __shared__ float w2s[32 * 33];
    __shared__ float b1s[32], g1s[32], be1s[32];
    __shared__ float b2s[32], g2s[32], be2s[32];

    int tid = threadIdx.x;
    for (int i = tid; i < 32 * FDIM; i += 256) w1s[i] = w1[i];
    for (int i = tid; i < 32 * 32;  i += 256) w2s[(i >> 5) * 33 + (i & 31)] = w2[i];
    if (tid < 32) {
        b1s[tid] = b1[tid]; g1s[tid] = g1[tid]; be1s[tid] = be1[tid];
        b2s[tid] = b2[tid]; g2s[tid] = g2[tid]; be2s[tid] = be2[tid];
    }
    __syncthreads();

    int warp = tid >> 5, lane = tid & 31;
    int e = blockIdx.x * 8 + warp;
    if (e >= E_TOTAL) return;

    float fv = (lane < FDIM) ? f[e * FDIM + lane] : 0.0f;
    float h = b1s[lane];
    #pragma unroll
    for (int k = 0; k < FDIM; k++) {
        float fk = __shfl_sync(0xffffffffu, fv, k);
        h = fmaf(fk, w1s[lane * FDIM + k], h);
    }
    float s = h;
    #pragma unroll
    for (int o = 16; o > 0; o >>= 1) s += __shfl_xor_sync(0xffffffffu, s, o);
    float mu = s * (1.0f / 32.0f);
    float d = h - mu;
    float v = d * d;
    #pragma unroll
    for (int o = 16; o > 0; o >>= 1) v += __shfl_xor_sync(0xffffffffu, v, o);
    float x = d * rsqrtf(v * (1.0f / 32.0f) + 1e-5f) * g1s[lane] + be1s[lane];
    x = fmaxf(x, 0.0f);

    float h2 = b2s[lane];
    #pragma unroll
    for (int k = 0; k < 32; k++) {
        float xk = __shfl_sync(0xffffffffu, x, k);
        h2 = fmaf(xk, w2s[lane * 33 + k], h2);
    }
    s = h2;
    #pragma unroll
    for (int o = 16; o > 0; o >>= 1) s += __shfl_xor_sync(0xffffffffu, s, o);
    mu = s * (1.0f / 32.0f);
    d = h2 - mu;
    v = d * d;
    #pragma unroll
    for (int o = 16; o > 0; o >>= 1) v += __shfl_xor_sync(0xffffffffu, v, o);
    float x2 = d * rsqrtf(v * (1.0f / 32.0f) + 1e-5f) * g2s[lane] + be2s[lane];
    x2 = fmaxf(x2, 0.0f);

    g_h[e * 32 + lane] = x2;
}

// ---------------------------------------------------------------------------
// Kernel 2: per edge, GEMM phase (thread = (co_r,ci), scalar FFMA, w3
// register-cached from XOR-swizzled smem) writes R triples to a 3KB smem
// bounce buffer; after a barrier the epilogue phase maps thread-linear j
// directly onto output float4 index -> fully coalesced STG.128.
// ---------------------------------------------------------------------------
__global__ __launch_bounds__(256, 2) void conv_kernel(
    const float* __restrict__ basis,
    const float* __restrict__ w3,
    const float* __restrict__ b3,
    float* __restrict__ out)
{
    extern __shared__ float smem[];
    float* w3s = smem;                            // 768 rows * 32 (XOR swizzle)
    float* h_s = w3s + W3S_ROWS * 32;             // TILE_E * 32
    float* B_s = h_s + TILE_E * 32;               // TILE_E * 36
    float* R_s = B_s + TILE_E * B_PITCH;          // 256 * 4 (R bounce)

    int tid = threadIdx.x;
    int e0  = blockIdx.x * TILE_E;
    int cy  = blockIdx.y;                         // 0..3

    // stage w3 slice with XOR swizzle: addr = row*32 + (k ^ (row&31))
    const float* w3g = w3 + (size_t)cy * (W3S_ROWS * 32);
    for (int i = tid; i < W3S_ROWS * 32; i += 256) {
        int row = i >> 5, k = i & 31;
        w3s[row * 32 + (k ^ (row & 31))] = w3g[i];
    }
    for (int i = tid; i < TILE_E * 32; i += 256)
        h_s[i] = g_h[(size_t)e0 * 32 + i];
    for (int i = tid; i < TILE_E * 27; i += 256) {
        int el = i / 27, j = i - el * 27;         // j = dd*9 + di*3 + q
        int dd = j / 9,  r = j - dd * 9;
        int di = r / 3,  q = r - di * 3;
        B_s[el * B_PITCH + dd * 12 + di * 4 + q] = basis[(size_t)e0 * 27 + i];
    }
    __syncthreads();

    // ---- one-time w3 register cache (96 floats) ----
    float w3r[96];
    #pragma unroll
    for (int ff = 0; ff < 3; ff++) {
        int row = tid * 3 + ff;
        int m = row & 31;
        const float* wr = w3s + row * 32;
        #pragma unroll
        for (int k = 0; k < 32; k++)
            w3r[ff * 32 + k] = wr[k ^ m];
    }

    int ci = tid & 31;
    int co = cy * CO_TILE + (tid >> 5);
    size_t jb = ((size_t)co * 32 + ci) * 3;
    float b30 = b3[jb], b31 = b3[jb + 1], b32 = b3[jb + 2];

    float4* Rs4 = reinterpret_cast<float4*>(R_s);

    for (int e = 0; e < TILE_E; e++) {
        // ================= GEMM phase =================
        const float* hp = h_s + e * 32;
        float R0 = b30, R1 = b31, R2 = b32;
        #pragma unroll
        for (int k4 = 0; k4 < 8; k4++) {
            float4 hv = *reinterpret_cast<const float4*>(hp + k4 * 4);
            R0 = fmaf(hv.x, w3r[0 * 32 + k4 * 4 + 0], R0);
            R1 = fmaf(hv.x, w3r[1 * 32 + k4 * 4 + 0], R1);
            R2 = fmaf(hv.x, w3r[2 * 32 + k4 * 4 + 0], R2);
            R0 = fmaf(hv.y, w3r[0 * 32 + k4 * 4 + 1], R0);
            R1 = fmaf(hv.y, w3r[1 * 32 + k4 * 4 + 1], R1);
            R2 = fmaf(hv.y, w3r[2 * 32 + k4 * 4 + 1], R2);
            R0 = fmaf(hv.z, w3r[0 * 32 + k4 * 4 + 2], R0);
            R1 = fmaf(hv.z, w3r[1 * 32 + k4 * 4 + 2], R1);
            R2 = fmaf(hv.z, w3r[2 * 32 + k4 * 4 + 2], R2);
            R0 = fmaf(hv.w, w3r[0 * 32 + k4 * 4 + 3], R0);
            R1 = fmaf(hv.w, w3r[1 * 32 + k4 * 4 + 3], R1);
            R2 = fmaf(hv.w, w3r[2 * 32 + k4 * 4 + 3], R2);
        }
        Rs4[tid] = make_float4(R0, R1, R2, 0.0f);
        __syncthreads();

        // ================= epilogue phase =================
        // 576 float4 per edge-CTA; j maps linearly to the output slab.
        const float4* Bq = reinterpret_cast<const float4*>(B_s + e * B_PITCH);
        float4* of4 = reinterpret_cast<float4*>(
            out + (size_t)(e0 + e) * 9216 + (size_t)cy * 2304);
        #pragma unroll
        for (int j = tid; j < 576; j += 256) {
            int row = j / 24;                     // 0..23 = co_r*3 + dd
            int cb  = j - row * 24;               // float4 block within row
            int co_r = row / 3, dd = row - co_r * 3;
            int c0   = cb * 4;
            int ci_a = (c0 * 0x5556) >> 16;       // c0/3 for c0<96
            int di0  = c0 - ci_a * 3;

            float4 Ra = Rs4[co_r * 32 + ci_a];
            float4 Rb = Rs4[co_r * 32 + ci_a + 1];
            float4 B0 = Bq[dd * 3 + 0];
            float4 B1 = Bq[dd * 3 + 1];
            float4 B2 = Bq[dd * 3 + 2];

            float da0 = fmaf(Ra.z, B0.z, fmaf(Ra.y, B0.y, Ra.x * B0.x));
            float da1 = fmaf(Ra.z, B1.z, fmaf(Ra.y, B1.y, Ra.x * B1.x));
            float da2 = fmaf(Ra.z, B2.z, fmaf(Ra.y, B2.y, Ra.x * B2.x));
            float db0 = fmaf(Rb.z, B0.z, fmaf(Rb.y, B0.y, Rb.x * B0.x));
            float db1 = fmaf(Rb.z, B1.z, fmaf(Rb.y, B1.y, Rb.x * B1.x));
            float db2 = fmaf(Rb.z, B2.z, fmaf(Rb.y, B2.y, Rb.x * B2.x));

            float4 v;
            v.x = di0 == 0 ? da0 : (di0 == 1 ? da1 : da2);
            v.y = di0 == 0 ? da1 : (di0 == 1 ? da2 : db0);
            v.z = di0 == 0 ? da2 : (di0 == 1 ? db0 : db1);
            v.w = di0 == 0 ? db0 : (di0 == 1 ? db1 : db2);
            of4[j] = v;
        }
        __syncthreads();
    }
}

// ---------------------------------------------------------------------------
extern "C" void kernel_launch(void* const* d_in, const int* in_sizes, int n_in,
                              void* d_out, int out_size)
{
    const float* f     = (const float*)d_in[0];
    const float* basis = (const float*)d_in[1];
    const float* w1    = (const float*)d_in[2];
    const float* b1    = (const float*)d_in[3];
    const float* g1    = (const float*)d_in[4];
    const float* be1   = (const float*)d_in[5];
    const float* w2    = (const float*)d_in[6];
    const float* b2    = (const float*)d_in[7];
    const float* g2    = (const float*)d_in[8];
    const float* be2   = (const float*)d_in[9];
    const float* w3    = (const float*)d_in[10];
    const float* b3    = (const float*)d_in[11];
    float* out = (float*)d_out;

    mlp_kernel<<<(E_TOTAL + 7) / 8, 256>>>(f, w1, b1, g1, be1, w2, b2, g2, be2);

    cudaFuncSetAttribute(conv_kernel,
                         cudaFuncAttributeMaxDynamicSharedMemorySize, SMEM_BYTES);
    dim3 grid(E_TOTAL / TILE_E, 32 / CO_TILE);
    conv_kernel<<<grid, 256, SMEM_BYTES>>>(basis, w3, b3, out);
}